// round 1
// baseline (speedup 1.0000x reference)
#include <cuda_runtime.h>
#include <math.h>

// Problem dims
#define BATCH   4096
#define D_IN    192
#define D_HID   512
#define D_OUT   128
#define N2      8192            // 2*BATCH
#define TEMP_INV 2.0f           // 1/0.5
#define BN_EPS   1e-5f

// ---------------- scratch (device globals; no allocation allowed) ----------
__device__ float g_y[N2 * D_HID];          // 16 MB: pre-BN activations (both heads)
__device__ float g_bn_scale[2 * D_HID];
__device__ float g_bn_bias[2 * D_HID];
__device__ float g_zraw[N2 * D_OUT];       // 4 MB
__device__ float g_z[N2 * D_OUT];          // 4 MB (L2-normalized)
__device__ float g_partial[8 * N2];        // per-colchunk partial sum-of-exp
__device__ float g_pos[N2];                // positive-pair sim (already /T)

// ============================================================================
// GEMM1: y = X @ W1^T + b1.  X = concat(h1,h2) rows, M=8192, N=512, K=192
// 64x64 tile, 256 threads, 4x4 micro, BK=32
// ============================================================================
__global__ __launch_bounds__(256) void gemm1_kernel(
    const float* __restrict__ h1, const float* __restrict__ h2,
    const float* __restrict__ W1, const float* __restrict__ b1)
{
    __shared__ float As[64][33];   // [m][k]
    __shared__ float Bs[32][65];   // [k][n]
    const int tid = threadIdx.x;
    const int tx = tid & 15, ty = tid >> 4;
    const int row0 = blockIdx.x * 64;
    const int col0 = blockIdx.y * 64;
    const float* A = (row0 < BATCH) ? h1 : h2;
    const int arow0 = (row0 < BATCH) ? row0 : (row0 - BATCH);

    float acc[4][4] = {};
    for (int kt = 0; kt < D_IN; kt += 32) {
        for (int idx = tid; idx < 64 * 32; idx += 256) {
            int m = idx >> 5, k = idx & 31;
            As[m][k] = A[(arow0 + m) * D_IN + kt + k];
        }
        for (int idx = tid; idx < 64 * 32; idx += 256) {
            int n = idx >> 5, k = idx & 31;
            Bs[k][n] = W1[(col0 + n) * D_IN + kt + k];
        }
        __syncthreads();
        #pragma unroll 8
        for (int k = 0; k < 32; k++) {
            float a[4], b[4];
            #pragma unroll
            for (int i = 0; i < 4; i++) a[i] = As[ty * 4 + i][k];
            #pragma unroll
            for (int j = 0; j < 4; j++) b[j] = Bs[k][tx * 4 + j];
            #pragma unroll
            for (int i = 0; i < 4; i++)
                #pragma unroll
                for (int j = 0; j < 4; j++)
                    acc[i][j] = fmaf(a[i], b[j], acc[i][j]);
        }
        __syncthreads();
    }
    #pragma unroll
    for (int i = 0; i < 4; i++) {
        int r = row0 + ty * 4 + i;
        #pragma unroll
        for (int j = 0; j < 4; j++) {
            int c = col0 + tx * 4 + j;
            g_y[r * D_HID + c] = acc[i][j] + b1[c];
        }
    }
}

// ============================================================================
// BN stats: per (head, column) mean/var over 4096 rows -> affine scale/bias
// grid (512/64, 2), block (64,4)
// ============================================================================
__global__ void bn_stats_kernel(const float* __restrict__ gamma,
                                const float* __restrict__ beta)
{
    const int c = blockIdx.x * 64 + threadIdx.x;
    const int head = blockIdx.y;
    const float* Y = g_y + head * BATCH * D_HID;
    float s = 0.f, sq = 0.f;
    for (int r = threadIdx.y; r < BATCH; r += 4) {
        float v = Y[r * D_HID + c];
        s += v; sq += v * v;
    }
    __shared__ float sh_s[4][64], sh_q[4][64];
    sh_s[threadIdx.y][threadIdx.x] = s;
    sh_q[threadIdx.y][threadIdx.x] = sq;
    __syncthreads();
    if (threadIdx.y == 0) {
        s  = sh_s[0][threadIdx.x] + sh_s[1][threadIdx.x] + sh_s[2][threadIdx.x] + sh_s[3][threadIdx.x];
        sq = sh_q[0][threadIdx.x] + sh_q[1][threadIdx.x] + sh_q[2][threadIdx.x] + sh_q[3][threadIdx.x];
        float mean = s * (1.0f / BATCH);
        float var  = sq * (1.0f / BATCH) - mean * mean;
        float a = gamma[c] * rsqrtf(var + BN_EPS);
        g_bn_scale[head * D_HID + c] = a;
        g_bn_bias[head * D_HID + c]  = beta[c] - mean * a;
    }
}

// ============================================================================
// GEMM2: zraw = relu(bn(y)) @ W2^T + b2.  M=8192, N=128, K=512
// 64x64 tile, 256 threads, 4x4 micro, BK=32; BN+ReLU fused on A load
// ============================================================================
__global__ __launch_bounds__(256) void gemm2_kernel(
    const float* __restrict__ W2, const float* __restrict__ b2)
{
    __shared__ float As[64][33];
    __shared__ float Bs[32][65];
    const int tid = threadIdx.x;
    const int tx = tid & 15, ty = tid >> 4;
    const int row0 = blockIdx.x * 64;
    const int col0 = blockIdx.y * 64;
    const int head = row0 >> 12;            // 64-row blocks never straddle 4096
    const float* sc = g_bn_scale + head * D_HID;
    const float* bi = g_bn_bias  + head * D_HID;

    float acc[4][4] = {};
    for (int kt = 0; kt < D_HID; kt += 32) {
        for (int idx = tid; idx < 64 * 32; idx += 256) {
            int m = idx >> 5, k = idx & 31;
            int kg = kt + k;
            float v = fmaf(g_y[(row0 + m) * D_HID + kg], sc[kg], bi[kg]);
            As[m][k] = fmaxf(v, 0.f);
        }
        for (int idx = tid; idx < 64 * 32; idx += 256) {
            int n = idx >> 5, k = idx & 31;
            Bs[k][n] = W2[(col0 + n) * D_HID + kt + k];
        }
        __syncthreads();
        #pragma unroll 8
        for (int k = 0; k < 32; k++) {
            float a[4], b[4];
            #pragma unroll
            for (int i = 0; i < 4; i++) a[i] = As[ty * 4 + i][k];
            #pragma unroll
            for (int j = 0; j < 4; j++) b[j] = Bs[k][tx * 4 + j];
            #pragma unroll
            for (int i = 0; i < 4; i++)
                #pragma unroll
                for (int j = 0; j < 4; j++)
                    acc[i][j] = fmaf(a[i], b[j], acc[i][j]);
        }
        __syncthreads();
    }
    #pragma unroll
    for (int i = 0; i < 4; i++) {
        int r = row0 + ty * 4 + i;
        #pragma unroll
        for (int j = 0; j < 4; j++) {
            int c = col0 + tx * 4 + j;
            g_zraw[r * D_OUT + c] = acc[i][j] + b2[c];
        }
    }
}

// ============================================================================
// L2 normalize rows of zraw -> g_z, and write z1/z2 into d_out (after loss slot)
// One warp per row; 8 rows per 256-thread block. grid = 1024.
// ============================================================================
__global__ void norm_kernel(float* __restrict__ out)
{
    const int row  = blockIdx.x * 8 + (threadIdx.x >> 5);
    const int lane = threadIdx.x & 31;
    const float4 v = ((const float4*)(g_zraw + row * D_OUT))[lane];
    float s = v.x * v.x + v.y * v.y + v.z * v.z + v.w * v.w;
    #pragma unroll
    for (int o = 16; o; o >>= 1) s += __shfl_xor_sync(0xffffffffu, s, o);
    const float inv = 1.0f / fmaxf(sqrtf(s), 1e-12f);
    float4 z = make_float4(v.x * inv, v.y * inv, v.z * inv, v.w * inv);
    ((float4*)(g_z + row * D_OUT))[lane] = z;
    // d_out layout: [loss(1), z1(4096*128), z2(4096*128)] -> flat offset 1 + row*128
    float* o4 = out + 1 + row * D_OUT + lane * 4;   // +1 breaks 16B align: scalar stores
    o4[0] = z.x; o4[1] = z.y; o4[2] = z.z; o4[3] = z.w;
}

// ============================================================================
// sim + partial sum-of-exp.
// Block: 128 rows x (8 tiles of 128 cols); 256 thr, 8x8 micro, K=128 resident.
// Grid (64, 8). Per-row partial sumexp (diag excluded) -> g_partial[by][row].
// Positive-pair sim captured inline -> g_pos.
// Dynamic smem: As 128*128 + Bs 128*132 floats = 133120 B.
// ============================================================================
#define SIM_SMEM_BYTES ((128 * 128 + 128 * 132) * 4)

__global__ __launch_bounds__(256) void sim_kernel()
{
    extern __shared__ float smem[];
    float* As = smem;                 // [m][k] row-major, 128x128
    float* Bs = smem + 128 * 128;     // [k][j] k-major, stride 132

    const int tid = threadIdx.x;
    const int tx = tid & 15, ty = tid >> 4;
    const int row0 = blockIdx.x * 128;

    // Load A tile once (row-major straight copy, float4)
    {
        const float4* Z4 = (const float4*)g_z;
        float4* As4 = (float4*)As;
        for (int idx = tid; idx < 128 * 32; idx += 256)
            As4[idx] = Z4[row0 * 32 + idx];
    }

    float rowAcc[8] = {};

    for (int ct = 0; ct < 8; ct++) {
        const int col0 = blockIdx.y * 1024 + ct * 128;
        __syncthreads();
        // Load B tile transposed: Bs[k][j] = z[col0+j][k]
        for (int idx = tid; idx < 128 * 128; idx += 256) {
            int m = idx >> 7, k = idx & 127;
            Bs[k * 132 + m] = g_z[(col0 + m) * D_OUT + k];
        }
        __syncthreads();

        float c[8][8] = {};
        #pragma unroll 4
        for (int k = 0; k < 128; k++) {
            float a[8], b[8];
            #pragma unroll
            for (int i = 0; i < 8; i++) a[i] = As[(ty * 8 + i) * 128 + k];
            float4 b0 = *(const float4*)&Bs[k * 132 + tx * 8];
            float4 b1 = *(const float4*)&Bs[k * 132 + tx * 8 + 4];
            b[0] = b0.x; b[1] = b0.y; b[2] = b0.z; b[3] = b0.w;
            b[4] = b1.x; b[5] = b1.y; b[6] = b1.z; b[7] = b1.w;
            #pragma unroll
            for (int i = 0; i < 8; i++)
                #pragma unroll
                for (int j = 0; j < 8; j++)
                    c[i][j] = fmaf(a[i], b[j], c[i][j]);
        }

        // exp + row partials; sim in [-2,2] so no max-shift needed
        #pragma unroll
        for (int r = 0; r < 8; r++) {
            const int i = row0 + ty * 8 + r;
            const int partner = (i + BATCH) & (N2 - 1);
            float s = 0.f;
            #pragma unroll
            for (int j = 0; j < 8; j++) {
                const int jj = col0 + tx * 8 + j;
                const float sim = c[r][j] * TEMP_INV;
                float e = __expf(sim);
                if (jj == i) e = 0.f;                 // exclude diagonal
                if (jj == partner) g_pos[i] = sim;    // single writer
                s += e;
            }
            rowAcc[r] += s;
        }
    }

    // reduce partials across tx (16 lanes within each half-warp), write partial
    #pragma unroll
    for (int r = 0; r < 8; r++) {
        float s = rowAcc[r];
        #pragma unroll
        for (int o = 8; o; o >>= 1) s += __shfl_xor_sync(0xffffffffu, s, o);
        if (tx == 0)
            g_partial[blockIdx.y * N2 + row0 + ty * 8 + r] = s;
    }
}

// ============================================================================
// loss = mean_i( log(sum_p partial[p][i]) - pos[i] )  (deterministic reduce)
// ============================================================================
__global__ void loss_kernel(float* __restrict__ out)
{
    __shared__ float sh[256];
    float s = 0.f;
    for (int i = threadIdx.x; i < N2; i += 256) {
        float se = 0.f;
        #pragma unroll
        for (int p = 0; p < 8; p++) se += g_partial[p * N2 + i];
        s += logf(se) - g_pos[i];
    }
    sh[threadIdx.x] = s;
    __syncthreads();
    for (int o = 128; o; o >>= 1) {
        if (threadIdx.x < o) sh[threadIdx.x] += sh[threadIdx.x + o];
        __syncthreads();
    }
    if (threadIdx.x == 0) out[0] = sh[0] * (1.0f / N2);
}

// ============================================================================
extern "C" void kernel_launch(void* const* d_in, const int* in_sizes, int n_in,
                              void* d_out, int out_size)
{
    const float* h1    = (const float*)d_in[0];
    const float* h2    = (const float*)d_in[1];
    const float* W1    = (const float*)d_in[2];
    const float* b1    = (const float*)d_in[3];
    const float* gamma = (const float*)d_in[4];
    const float* beta  = (const float*)d_in[5];
    const float* W2    = (const float*)d_in[6];
    const float* b2    = (const float*)d_in[7];
    float* out = (float*)d_out;

    cudaFuncSetAttribute(sim_kernel, cudaFuncAttributeMaxDynamicSharedMemorySize,
                         SIM_SMEM_BYTES);

    gemm1_kernel<<<dim3(N2 / 64, D_HID / 64), 256>>>(h1, h2, W1, b1);
    bn_stats_kernel<<<dim3(D_HID / 64, 2), dim3(64, 4)>>>(gamma, beta);
    gemm2_kernel<<<dim3(N2 / 64, D_OUT / 64), 256>>>(W2, b2);
    norm_kernel<<<N2 / 8, 256>>>(out);
    sim_kernel<<<dim3(64, 8), 256, SIM_SMEM_BYTES>>>();
    loss_kernel<<<1, 256>>>(out);
}

// round 3
// speedup vs baseline: 2.8812x; 2.8812x over previous
#include <cuda_runtime.h>
#include <cuda_bf16.h>
#include <math.h>
#include <stdint.h>

// Problem dims
#define BATCH   4096
#define D_IN    192
#define D_HID   512
#define D_OUT   128
#define N2      8192            // 2*BATCH
#define TEMP_INV 2.0f           // 1/0.5
#define BN_EPS   1e-5f

// ---------------- scratch (device globals; no allocation allowed) ----------
__device__ float g_y[N2 * D_HID];          // 16 MB: pre-BN activations
__device__ float g_bn_scale[2 * D_HID];
__device__ float g_bn_bias[2 * D_HID];
__device__ float g_zraw[N2 * D_OUT];       // 4 MB
__device__ float g_z[N2 * D_OUT];          // 4 MB (L2-normalized, fp32)
__device__ __nv_bfloat16 g_zh[N2 * D_OUT]; // 2 MB (bf16 copy for tensor GEMM)
__device__ float g_partial[8 * N2];        // per-colslab partial sum-of-exp
__device__ float g_pos[N2];                // positive-pair sim (fp32 exact, /T)

// ============================================================================
// GEMM1: y = X @ W1^T + b1.  M=8192, N=512, K=192 (fp32)
// ============================================================================
__global__ __launch_bounds__(256) void gemm1_kernel(
    const float* __restrict__ h1, const float* __restrict__ h2,
    const float* __restrict__ W1, const float* __restrict__ b1)
{
    __shared__ float As[64][33];
    __shared__ float Bs[32][65];
    const int tid = threadIdx.x;
    const int tx = tid & 15, ty = tid >> 4;
    const int row0 = blockIdx.x * 64;
    const int col0 = blockIdx.y * 64;
    const float* A = (row0 < BATCH) ? h1 : h2;
    const int arow0 = (row0 < BATCH) ? row0 : (row0 - BATCH);

    float acc[4][4] = {};
    for (int kt = 0; kt < D_IN; kt += 32) {
        for (int idx = tid; idx < 64 * 32; idx += 256) {
            int m = idx >> 5, k = idx & 31;
            As[m][k] = A[(arow0 + m) * D_IN + kt + k];
        }
        for (int idx = tid; idx < 64 * 32; idx += 256) {
            int n = idx >> 5, k = idx & 31;
            Bs[k][n] = W1[(col0 + n) * D_IN + kt + k];
        }
        __syncthreads();
        #pragma unroll 8
        for (int k = 0; k < 32; k++) {
            float a[4], b[4];
            #pragma unroll
            for (int i = 0; i < 4; i++) a[i] = As[ty * 4 + i][k];
            #pragma unroll
            for (int j = 0; j < 4; j++) b[j] = Bs[k][tx * 4 + j];
            #pragma unroll
            for (int i = 0; i < 4; i++)
                #pragma unroll
                for (int j = 0; j < 4; j++)
                    acc[i][j] = fmaf(a[i], b[j], acc[i][j]);
        }
        __syncthreads();
    }
    #pragma unroll
    for (int i = 0; i < 4; i++) {
        int r = row0 + ty * 4 + i;
        #pragma unroll
        for (int j = 0; j < 4; j++) {
            int c = col0 + tx * 4 + j;
            g_y[r * D_HID + c] = acc[i][j] + b1[c];
        }
    }
}

// ============================================================================
// BN stats: per (head, column) mean/var over 4096 rows -> affine scale/bias
// ============================================================================
__global__ void bn_stats_kernel(const float* __restrict__ gamma,
                                const float* __restrict__ beta)
{
    const int c = blockIdx.x * 64 + threadIdx.x;
    const int head = blockIdx.y;
    const float* Y = g_y + head * BATCH * D_HID;
    float s = 0.f, sq = 0.f;
    for (int r = threadIdx.y; r < BATCH; r += 4) {
        float v = Y[r * D_HID + c];
        s += v; sq += v * v;
    }
    __shared__ float sh_s[4][64], sh_q[4][64];
    sh_s[threadIdx.y][threadIdx.x] = s;
    sh_q[threadIdx.y][threadIdx.x] = sq;
    __syncthreads();
    if (threadIdx.y == 0) {
        s  = sh_s[0][threadIdx.x] + sh_s[1][threadIdx.x] + sh_s[2][threadIdx.x] + sh_s[3][threadIdx.x];
        sq = sh_q[0][threadIdx.x] + sh_q[1][threadIdx.x] + sh_q[2][threadIdx.x] + sh_q[3][threadIdx.x];
        float mean = s * (1.0f / BATCH);
        float var  = sq * (1.0f / BATCH) - mean * mean;
        float a = gamma[c] * rsqrtf(var + BN_EPS);
        g_bn_scale[head * D_HID + c] = a;
        g_bn_bias[head * D_HID + c]  = beta[c] - mean * a;
    }
}

// ============================================================================
// GEMM2: zraw = relu(bn(y)) @ W2^T + b2.  M=8192, N=128, K=512 (fp32)
// ============================================================================
__global__ __launch_bounds__(256) void gemm2_kernel(
    const float* __restrict__ W2, const float* __restrict__ b2)
{
    __shared__ float As[64][33];
    __shared__ float Bs[32][65];
    const int tid = threadIdx.x;
    const int tx = tid & 15, ty = tid >> 4;
    const int row0 = blockIdx.x * 64;
    const int col0 = blockIdx.y * 64;
    const int head = row0 >> 12;
    const float* sc = g_bn_scale + head * D_HID;
    const float* bi = g_bn_bias  + head * D_HID;

    float acc[4][4] = {};
    for (int kt = 0; kt < D_HID; kt += 32) {
        for (int idx = tid; idx < 64 * 32; idx += 256) {
            int m = idx >> 5, k = idx & 31;
            int kg = kt + k;
            float v = fmaf(g_y[(row0 + m) * D_HID + kg], sc[kg], bi[kg]);
            As[m][k] = fmaxf(v, 0.f);
        }
        for (int idx = tid; idx < 64 * 32; idx += 256) {
            int n = idx >> 5, k = idx & 31;
            Bs[k][n] = W2[(col0 + n) * D_HID + kt + k];
        }
        __syncthreads();
        #pragma unroll 8
        for (int k = 0; k < 32; k++) {
            float a[4], b[4];
            #pragma unroll
            for (int i = 0; i < 4; i++) a[i] = As[ty * 4 + i][k];
            #pragma unroll
            for (int j = 0; j < 4; j++) b[j] = Bs[k][tx * 4 + j];
            #pragma unroll
            for (int i = 0; i < 4; i++)
                #pragma unroll
                for (int j = 0; j < 4; j++)
                    acc[i][j] = fmaf(a[i], b[j], acc[i][j]);
        }
        __syncthreads();
    }
    #pragma unroll
    for (int i = 0; i < 4; i++) {
        int r = row0 + ty * 4 + i;
        #pragma unroll
        for (int j = 0; j < 4; j++) {
            int c = col0 + tx * 4 + j;
            g_zraw[r * D_OUT + c] = acc[i][j] + b2[c];
        }
    }
}

// ============================================================================
// L2 normalize; emit fp32 (d_out + g_z) and bf16 (g_zh)
// ============================================================================
__global__ void norm_kernel(float* __restrict__ out)
{
    const int row  = blockIdx.x * 8 + (threadIdx.x >> 5);
    const int lane = threadIdx.x & 31;
    const float4 v = ((const float4*)(g_zraw + row * D_OUT))[lane];
    float s = v.x * v.x + v.y * v.y + v.z * v.z + v.w * v.w;
    #pragma unroll
    for (int o = 16; o; o >>= 1) s += __shfl_xor_sync(0xffffffffu, s, o);
    const float inv = 1.0f / fmaxf(sqrtf(s), 1e-12f);
    float4 z = make_float4(v.x * inv, v.y * inv, v.z * inv, v.w * inv);
    ((float4*)(g_z + row * D_OUT))[lane] = z;
    __nv_bfloat162* zh2 = (__nv_bfloat162*)(g_zh + row * D_OUT);
    zh2[lane * 2 + 0] = __nv_bfloat162(__float2bfloat16(z.x), __float2bfloat16(z.y));
    zh2[lane * 2 + 1] = __nv_bfloat162(__float2bfloat16(z.z), __float2bfloat16(z.w));
    float* o4 = out + 1 + row * D_OUT + lane * 4;   // +1 breaks 16B align
    o4[0] = z.x; o4[1] = z.y; o4[2] = z.z; o4[3] = z.w;
}

// ============================================================================
// pos[i] = (z1_i . z2_i) / T in exact fp32 (one warp per pair)
// ============================================================================
__global__ void pos_kernel()
{
    const int i    = blockIdx.x * 8 + (threadIdx.x >> 5);
    const int lane = threadIdx.x & 31;
    const float4 a = ((const float4*)(g_z + i * D_OUT))[lane];
    const float4 b = ((const float4*)(g_z + (i + BATCH) * D_OUT))[lane];
    float s = a.x * b.x + a.y * b.y + a.z * b.z + a.w * b.w;
    #pragma unroll
    for (int o = 16; o; o >>= 1) s += __shfl_xor_sync(0xffffffffu, s, o);
    if (lane == 0) {
        float p = s * TEMP_INV;
        g_pos[i] = p;
        g_pos[i + BATCH] = p;
    }
}

// ============================================================================
// sim via legacy warp MMA (bf16, fp32 accum): compiles for plain sm_103.
// Block 256 thr (8 warps, 2x4), tile 128x128, K=128 resident.
// Grid (64, 8): row block 128, col slab 1024 (8 tiles of 128).
// SMEM tiles padded to stride 136 bf16 (+4 banks/row -> conflict-free).
// Epilogue: exp(2*sim), zero diag, per-row partial -> g_partial[by][row].
// ============================================================================
#define SIM_TILE_STRIDE 136                        // bf16 elements per row
#define SIM_SMEM_BYTES  (2 * 128 * SIM_TILE_STRIDE * 2)   // 69632

__device__ __forceinline__ void mma_bf16(float* c, const uint32_t* a, const uint32_t* b)
{
    asm volatile(
        "mma.sync.aligned.m16n8k16.row.col.f32.bf16.bf16.f32 "
        "{%0,%1,%2,%3}, {%4,%5,%6,%7}, {%8,%9}, {%0,%1,%2,%3};"
        : "+f"(c[0]), "+f"(c[1]), "+f"(c[2]), "+f"(c[3])
        : "r"(a[0]), "r"(a[1]), "r"(a[2]), "r"(a[3]), "r"(b[0]), "r"(b[1]));
}

__global__ __launch_bounds__(256) void sim_kernel()
{
    extern __shared__ __nv_bfloat16 smem_bf[];
    __nv_bfloat16* As = smem_bf;                       // [128][136]
    __nv_bfloat16* Bs = smem_bf + 128 * SIM_TILE_STRIDE;

    const int tid  = threadIdx.x;
    const int wid  = tid >> 5, lane = tid & 31;
    const int g    = lane >> 2, tq = lane & 3;
    const int wr   = (wid >> 2) * 64;                  // warp row base (0/64)
    const int wn   = wid & 3;                          // warp col group
    const int wc   = wn * 32;                          // warp col base
    const int row0 = blockIdx.x * 128;

    // Load A tile once: 128 rows x 16 uint4 (row stride 17 uint4 = 136 bf16)
    {
        const uint4* src = (const uint4*)(g_zh + row0 * D_OUT);
        uint4* dst = (uint4*)As;
        for (int idx = tid; idx < 2048; idx += 256) {
            int r = idx >> 4, c = idx & 15;
            dst[r * 17 + c] = src[idx];
        }
    }

    float rowAcc[4][2] = {};   // [mi][row-low / row-high(+8)]

    for (int ct = 0; ct < 8; ct++) {
        const int col0 = blockIdx.y * 1024 + ct * 128;
        __syncthreads();       // previous iter done reading Bs
        {
            const uint4* src = (const uint4*)(g_zh + col0 * D_OUT);
            uint4* dst = (uint4*)Bs;
            for (int idx = tid; idx < 2048; idx += 256) {
                int r = idx >> 4, c = idx & 15;
                dst[r * 17 + c] = src[idx];
            }
        }
        __syncthreads();

        float acc[4][4][4] = {};
        #pragma unroll
        for (int kk = 0; kk < 128; kk += 16) {
            uint32_t a[4][4], b[4][2];
            #pragma unroll
            for (int mi = 0; mi < 4; mi++) {
                const __nv_bfloat16* ap = As + (wr + mi * 16 + g) * SIM_TILE_STRIDE + kk + tq * 2;
                a[mi][0] = *(const uint32_t*)ap;                          // (g,   k)
                a[mi][1] = *(const uint32_t*)(ap + 8 * SIM_TILE_STRIDE);  // (g+8, k)
                a[mi][2] = *(const uint32_t*)(ap + 8);                    // (g,   k+8)
                a[mi][3] = *(const uint32_t*)(ap + 8 * SIM_TILE_STRIDE + 8);
            }
            #pragma unroll
            for (int ni = 0; ni < 4; ni++) {
                const __nv_bfloat16* bp = Bs + (wc + ni * 8 + g) * SIM_TILE_STRIDE + kk + tq * 2;
                b[ni][0] = *(const uint32_t*)bp;        // (n=g, k)
                b[ni][1] = *(const uint32_t*)(bp + 8);  // (n=g, k+8)
            }
            #pragma unroll
            for (int mi = 0; mi < 4; mi++)
                #pragma unroll
                for (int ni = 0; ni < 4; ni++)
                    mma_bf16(acc[mi][ni], a[mi], b[ni]);
        }

        // Epilogue: exp(2*sim), exclude diagonal, accumulate per-row partials
        #pragma unroll
        for (int mi = 0; mi < 4; mi++) {
            const int r0 = row0 + wr + mi * 16 + g;
            const int r1 = r0 + 8;
            #pragma unroll
            for (int ni = 0; ni < 4; ni++) {
                const int j0 = col0 + wc + ni * 8 + tq * 2;
                float e00 = __expf(2.0f * acc[mi][ni][0]); if (j0     == r0) e00 = 0.f;
                float e01 = __expf(2.0f * acc[mi][ni][1]); if (j0 + 1 == r0) e01 = 0.f;
                float e10 = __expf(2.0f * acc[mi][ni][2]); if (j0     == r1) e10 = 0.f;
                float e11 = __expf(2.0f * acc[mi][ni][3]); if (j0 + 1 == r1) e11 = 0.f;
                rowAcc[mi][0] += e00 + e01;
                rowAcc[mi][1] += e10 + e11;
            }
        }
    }

    // Reduce across the 4 tq lanes (bits 0-1 of lane)
    #pragma unroll
    for (int mi = 0; mi < 4; mi++)
        #pragma unroll
        for (int h = 0; h < 2; h++) {
            float s = rowAcc[mi][h];
            s += __shfl_xor_sync(0xffffffffu, s, 1);
            s += __shfl_xor_sync(0xffffffffu, s, 2);
            rowAcc[mi][h] = s;
        }

    __syncthreads();                      // done reading As/Bs; reuse as reduce buf
    float* red = (float*)smem_bf;         // [4 colgroups][128 rows]
    if (tq == 0) {
        #pragma unroll
        for (int mi = 0; mi < 4; mi++) {
            red[wn * 128 + wr + mi * 16 + g]     = rowAcc[mi][0];
            red[wn * 128 + wr + mi * 16 + g + 8] = rowAcc[mi][1];
        }
    }
    __syncthreads();
    if (tid < 128) {
        float s = red[tid] + red[128 + tid] + red[256 + tid] + red[384 + tid];
        g_partial[blockIdx.y * N2 + row0 + tid] = s;
    }
}

// ============================================================================
// loss = mean_i( log(sum_p partial[p][i]) - pos[i] )
// ============================================================================
__global__ void loss_kernel(float* __restrict__ out)
{
    __shared__ float sh[256];
    float s = 0.f;
    for (int i = threadIdx.x; i < N2; i += 256) {
        float se = 0.f;
        #pragma unroll
        for (int p = 0; p < 8; p++) se += g_partial[p * N2 + i];
        s += logf(se) - g_pos[i];
    }
    sh[threadIdx.x] = s;
    __syncthreads();
    for (int o = 128; o; o >>= 1) {
        if (threadIdx.x < o) sh[threadIdx.x] += sh[threadIdx.x + o];
        __syncthreads();
    }
    if (threadIdx.x == 0) out[0] = sh[0] * (1.0f / N2);
}

// ============================================================================
extern "C" void kernel_launch(void* const* d_in, const int* in_sizes, int n_in,
                              void* d_out, int out_size)
{
    const float* h1    = (const float*)d_in[0];
    const float* h2    = (const float*)d_in[1];
    const float* W1    = (const float*)d_in[2];
    const float* b1    = (const float*)d_in[3];
    const float* gamma = (const float*)d_in[4];
    const float* beta  = (const float*)d_in[5];
    const float* W2    = (const float*)d_in[6];
    const float* b2    = (const float*)d_in[7];
    float* out = (float*)d_out;

    cudaFuncSetAttribute(sim_kernel, cudaFuncAttributeMaxDynamicSharedMemorySize,
                         SIM_SMEM_BYTES);

    gemm1_kernel<<<dim3(N2 / 64, D_HID / 64), 256>>>(h1, h2, W1, b1);
    bn_stats_kernel<<<dim3(D_HID / 64, 2), dim3(64, 4)>>>(gamma, beta);
    gemm2_kernel<<<dim3(N2 / 64, D_OUT / 64), 256>>>(W2, b2);
    norm_kernel<<<N2 / 8, 256>>>(out);
    pos_kernel<<<BATCH / 8, 256>>>();
    sim_kernel<<<dim3(64, 8), 256, SIM_SMEM_BYTES>>>();
    loss_kernel<<<1, 256>>>(out);
}

// round 4
// speedup vs baseline: 4.1267x; 1.4323x over previous
#include <cuda_runtime.h>
#include <cuda_bf16.h>
#include <math.h>
#include <stdint.h>

// Problem dims
#define BATCH   4096
#define D_IN    192
#define D_HID   512
#define D_OUT   128
#define N2      8192            // 2*BATCH
#define TEMP_INV 2.0f           // 1/0.5
#define BN_EPS   1e-5f

// ---------------- scratch (device globals; no allocation allowed) ----------
__device__ float g_y[N2 * D_HID];          // 16 MB: pre-BN activations
__device__ float g_bn_scale[2 * D_HID];
__device__ float g_bn_bias[2 * D_HID];
__device__ float g_zraw[N2 * D_OUT];       // 4 MB
__device__ float g_z[N2 * D_OUT];          // 4 MB (L2-normalized, fp32)
__device__ __nv_bfloat16 g_zh[N2 * D_OUT]; // 2 MB (bf16 copy for sim GEMM)
__device__ float g_partial[8 * N2];        // per-colslab partial sum-of-exp
__device__ float g_pos[N2];                // positive-pair sim (fp32 exact, /T)

// ============================================================================
// MMA helpers (legacy warp-level mma.sync — plain PTX, works on sm_103 target)
// ============================================================================
__device__ __forceinline__ float to_tf32(float x) {
    float r;
    asm("cvt.rna.tf32.f32 %0, %1;" : "=f"(r) : "f"(x));
    return r;
}
__device__ __forceinline__ void mma_tf32(float* c, const uint32_t* a, const uint32_t* b)
{
    asm volatile(
        "mma.sync.aligned.m16n8k8.row.col.f32.tf32.tf32.f32 "
        "{%0,%1,%2,%3}, {%4,%5,%6,%7}, {%8,%9}, {%0,%1,%2,%3};"
        : "+f"(c[0]), "+f"(c[1]), "+f"(c[2]), "+f"(c[3])
        : "r"(a[0]), "r"(a[1]), "r"(a[2]), "r"(a[3]), "r"(b[0]), "r"(b[1]));
}
__device__ __forceinline__ void mma_bf16(float* c, const uint32_t* a, const uint32_t* b)
{
    asm volatile(
        "mma.sync.aligned.m16n8k16.row.col.f32.bf16.bf16.f32 "
        "{%0,%1,%2,%3}, {%4,%5,%6,%7}, {%8,%9}, {%0,%1,%2,%3};"
        : "+f"(c[0]), "+f"(c[1]), "+f"(c[2]), "+f"(c[3])
        : "r"(a[0]), "r"(a[1]), "r"(a[2]), "r"(a[3]), "r"(b[0]), "r"(b[1]));
}

// ============================================================================
// GEMM1 (tf32): y = X @ W1^T + b1.  M=8192, N=512, K=192
// Block 256 thr (8 warps, 4 row x 2 col), tile 128x64, BK=32.
// ============================================================================
#define G1_AS 36    // padded stride (floats); banks (4g+tq) conflict-free
__global__ __launch_bounds__(256) void gemm1_kernel(
    const float* __restrict__ h1, const float* __restrict__ h2,
    const float* __restrict__ W1, const float* __restrict__ b1)
{
    __shared__ float As[128][G1_AS];
    __shared__ float Bs[64][G1_AS];
    const int tid  = threadIdx.x;
    const int wid  = tid >> 5, lane = tid & 31;
    const int g    = lane >> 2, tq = lane & 3;
    const int wr   = (wid >> 1) * 32;
    const int wc   = (wid & 1) * 32;
    const int row0 = blockIdx.x * 128;
    const int col0 = blockIdx.y * 64;
    const float* A = (row0 < BATCH) ? h1 : h2;
    const int arow0 = (row0 < BATCH) ? row0 : (row0 - BATCH);

    float acc[2][4][4] = {};

    for (int kt = 0; kt < D_IN; kt += 32) {
        const int kt4 = kt >> 2;
        // A: 128 rows x 8 float4
        #pragma unroll
        for (int it = 0; it < 4; it++) {
            int idx = tid + it * 256;           // 0..1023
            int r = idx >> 3, c = idx & 7;
            float4 v = ((const float4*)A)[(arow0 + r) * 48 + kt4 + c];
            float* d = &As[r][c * 4];
            d[0] = to_tf32(v.x); d[1] = to_tf32(v.y);
            d[2] = to_tf32(v.z); d[3] = to_tf32(v.w);
        }
        // B: 64 rows x 8 float4
        #pragma unroll
        for (int it = 0; it < 2; it++) {
            int idx = tid + it * 256;           // 0..511
            int r = idx >> 3, c = idx & 7;
            float4 v = ((const float4*)W1)[(col0 + r) * 48 + kt4 + c];
            float* d = &Bs[r][c * 4];
            d[0] = to_tf32(v.x); d[1] = to_tf32(v.y);
            d[2] = to_tf32(v.z); d[3] = to_tf32(v.w);
        }
        __syncthreads();
        #pragma unroll
        for (int kk = 0; kk < 4; kk++) {
            uint32_t a[2][4], b[4][2];
            #pragma unroll
            for (int mi = 0; mi < 2; mi++) {
                const uint32_t* ap = (const uint32_t*)&As[wr + mi * 16 + g][kk * 8 + tq];
                a[mi][0] = ap[0];
                a[mi][1] = ap[8 * G1_AS];
                a[mi][2] = ap[4];
                a[mi][3] = ap[8 * G1_AS + 4];
            }
            #pragma unroll
            for (int ni = 0; ni < 4; ni++) {
                const uint32_t* bp = (const uint32_t*)&Bs[wc + ni * 8 + g][kk * 8 + tq];
                b[ni][0] = bp[0];
                b[ni][1] = bp[4];
            }
            #pragma unroll
            for (int mi = 0; mi < 2; mi++)
                #pragma unroll
                for (int ni = 0; ni < 4; ni++)
                    mma_tf32(acc[mi][ni], a[mi], b[ni]);
        }
        __syncthreads();
    }
    #pragma unroll
    for (int mi = 0; mi < 2; mi++) {
        const int r0 = row0 + wr + mi * 16 + g;
        #pragma unroll
        for (int ni = 0; ni < 4; ni++) {
            const int c0 = col0 + wc + ni * 8 + tq * 2;
            g_y[r0 * D_HID + c0]           = acc[mi][ni][0] + b1[c0];
            g_y[r0 * D_HID + c0 + 1]       = acc[mi][ni][1] + b1[c0 + 1];
            g_y[(r0 + 8) * D_HID + c0]     = acc[mi][ni][2] + b1[c0];
            g_y[(r0 + 8) * D_HID + c0 + 1] = acc[mi][ni][3] + b1[c0 + 1];
        }
    }
}

// ============================================================================
// BN stats: per (head, column) mean/var over 4096 rows -> affine scale/bias
// ============================================================================
__global__ void bn_stats_kernel(const float* __restrict__ gamma,
                                const float* __restrict__ beta)
{
    const int c = blockIdx.x * 64 + threadIdx.x;
    const int head = blockIdx.y;
    const float* Y = g_y + head * BATCH * D_HID;
    float s = 0.f, sq = 0.f;
    for (int r = threadIdx.y; r < BATCH; r += 4) {
        float v = Y[r * D_HID + c];
        s += v; sq += v * v;
    }
    __shared__ float sh_s[4][64], sh_q[4][64];
    sh_s[threadIdx.y][threadIdx.x] = s;
    sh_q[threadIdx.y][threadIdx.x] = sq;
    __syncthreads();
    if (threadIdx.y == 0) {
        s  = sh_s[0][threadIdx.x] + sh_s[1][threadIdx.x] + sh_s[2][threadIdx.x] + sh_s[3][threadIdx.x];
        sq = sh_q[0][threadIdx.x] + sh_q[1][threadIdx.x] + sh_q[2][threadIdx.x] + sh_q[3][threadIdx.x];
        float mean = s * (1.0f / BATCH);
        float var  = sq * (1.0f / BATCH) - mean * mean;
        float a = gamma[c] * rsqrtf(var + BN_EPS);
        g_bn_scale[head * D_HID + c] = a;
        g_bn_bias[head * D_HID + c]  = beta[c] - mean * a;
    }
}

// ============================================================================
// GEMM2 (tf32): zraw = relu(bn(y)) @ W2^T + b2.  M=8192, N=128, K=512
// Same structure; BN+ReLU+tf32 fused on A smem store. Grid (64, 2).
// ============================================================================
__global__ __launch_bounds__(256) void gemm2_kernel(
    const float* __restrict__ W2, const float* __restrict__ b2)
{
    __shared__ float As[128][G1_AS];
    __shared__ float Bs[64][G1_AS];
    const int tid  = threadIdx.x;
    const int wid  = tid >> 5, lane = tid & 31;
    const int g    = lane >> 2, tq = lane & 3;
    const int wr   = (wid >> 1) * 32;
    const int wc   = (wid & 1) * 32;
    const int row0 = blockIdx.x * 128;
    const int col0 = blockIdx.y * 64;
    const int head = row0 >> 12;
    const float* sc = g_bn_scale + head * D_HID;
    const float* bi = g_bn_bias  + head * D_HID;

    float acc[2][4][4] = {};

    for (int kt = 0; kt < D_HID; kt += 32) {
        const int kt4 = kt >> 2;
        #pragma unroll
        for (int it = 0; it < 4; it++) {
            int idx = tid + it * 256;
            int r = idx >> 3, c = idx & 7;
            float4 v = ((const float4*)g_y)[(row0 + r) * 128 + kt4 + c];
            float4 s4 = ((const float4*)sc)[kt4 + c];
            float4 o4 = ((const float4*)bi)[kt4 + c];
            float* d = &As[r][c * 4];
            d[0] = to_tf32(fmaxf(fmaf(v.x, s4.x, o4.x), 0.f));
            d[1] = to_tf32(fmaxf(fmaf(v.y, s4.y, o4.y), 0.f));
            d[2] = to_tf32(fmaxf(fmaf(v.z, s4.z, o4.z), 0.f));
            d[3] = to_tf32(fmaxf(fmaf(v.w, s4.w, o4.w), 0.f));
        }
        #pragma unroll
        for (int it = 0; it < 2; it++) {
            int idx = tid + it * 256;
            int r = idx >> 3, c = idx & 7;
            float4 v = ((const float4*)W2)[(col0 + r) * 128 + kt4 + c];
            float* d = &Bs[r][c * 4];
            d[0] = to_tf32(v.x); d[1] = to_tf32(v.y);
            d[2] = to_tf32(v.z); d[3] = to_tf32(v.w);
        }
        __syncthreads();
        #pragma unroll
        for (int kk = 0; kk < 4; kk++) {
            uint32_t a[2][4], b[4][2];
            #pragma unroll
            for (int mi = 0; mi < 2; mi++) {
                const uint32_t* ap = (const uint32_t*)&As[wr + mi * 16 + g][kk * 8 + tq];
                a[mi][0] = ap[0];
                a[mi][1] = ap[8 * G1_AS];
                a[mi][2] = ap[4];
                a[mi][3] = ap[8 * G1_AS + 4];
            }
            #pragma unroll
            for (int ni = 0; ni < 4; ni++) {
                const uint32_t* bp = (const uint32_t*)&Bs[wc + ni * 8 + g][kk * 8 + tq];
                b[ni][0] = bp[0];
                b[ni][1] = bp[4];
            }
            #pragma unroll
            for (int mi = 0; mi < 2; mi++)
                #pragma unroll
                for (int ni = 0; ni < 4; ni++)
                    mma_tf32(acc[mi][ni], a[mi], b[ni]);
        }
        __syncthreads();
    }
    #pragma unroll
    for (int mi = 0; mi < 2; mi++) {
        const int r0 = row0 + wr + mi * 16 + g;
        #pragma unroll
        for (int ni = 0; ni < 4; ni++) {
            const int c0 = col0 + wc + ni * 8 + tq * 2;
            g_zraw[r0 * D_OUT + c0]           = acc[mi][ni][0] + b2[c0];
            g_zraw[r0 * D_OUT + c0 + 1]       = acc[mi][ni][1] + b2[c0 + 1];
            g_zraw[(r0 + 8) * D_OUT + c0]     = acc[mi][ni][2] + b2[c0];
            g_zraw[(r0 + 8) * D_OUT + c0 + 1] = acc[mi][ni][3] + b2[c0 + 1];
        }
    }
}

// ============================================================================
// L2 normalize; emit fp32 (d_out + g_z) and bf16 (g_zh)
// ============================================================================
__global__ void norm_kernel(float* __restrict__ out)
{
    const int row  = blockIdx.x * 8 + (threadIdx.x >> 5);
    const int lane = threadIdx.x & 31;
    const float4 v = ((const float4*)(g_zraw + row * D_OUT))[lane];
    float s = v.x * v.x + v.y * v.y + v.z * v.z + v.w * v.w;
    #pragma unroll
    for (int o = 16; o; o >>= 1) s += __shfl_xor_sync(0xffffffffu, s, o);
    const float inv = 1.0f / fmaxf(sqrtf(s), 1e-12f);
    float4 z = make_float4(v.x * inv, v.y * inv, v.z * inv, v.w * inv);
    ((float4*)(g_z + row * D_OUT))[lane] = z;
    __nv_bfloat162* zh2 = (__nv_bfloat162*)(g_zh + row * D_OUT);
    zh2[lane * 2 + 0] = __nv_bfloat162(__float2bfloat16(z.x), __float2bfloat16(z.y));
    zh2[lane * 2 + 1] = __nv_bfloat162(__float2bfloat16(z.z), __float2bfloat16(z.w));
    float* o4 = out + 1 + row * D_OUT + lane * 4;   // +1 breaks 16B align
    o4[0] = z.x; o4[1] = z.y; o4[2] = z.z; o4[3] = z.w;
}

// ============================================================================
// pos[i] = (z1_i . z2_i) / T in exact fp32 (one warp per pair)
// ============================================================================
__global__ void pos_kernel()
{
    const int i    = blockIdx.x * 8 + (threadIdx.x >> 5);
    const int lane = threadIdx.x & 31;
    const float4 a = ((const float4*)(g_z + i * D_OUT))[lane];
    const float4 b = ((const float4*)(g_z + (i + BATCH) * D_OUT))[lane];
    float s = a.x * b.x + a.y * b.y + a.z * b.z + a.w * b.w;
    #pragma unroll
    for (int o = 16; o; o >>= 1) s += __shfl_xor_sync(0xffffffffu, s, o);
    if (lane == 0) {
        float p = s * TEMP_INV;
        g_pos[i] = p;
        g_pos[i + BATCH] = p;
    }
}

// ============================================================================
// sim via bf16 mma.sync. Block 256 thr (8 warps, 2x4), tile 128x128, K=128.
// Grid (64, 8). Epilogue: exp(2*sim), zero diag, per-row partial.
// ============================================================================
#define SIM_TILE_STRIDE 136
#define SIM_SMEM_BYTES  (2 * 128 * SIM_TILE_STRIDE * 2)   // 69632

__global__ __launch_bounds__(256) void sim_kernel()
{
    extern __shared__ __nv_bfloat16 smem_bf[];
    __nv_bfloat16* As = smem_bf;
    __nv_bfloat16* Bs = smem_bf + 128 * SIM_TILE_STRIDE;

    const int tid  = threadIdx.x;
    const int wid  = tid >> 5, lane = tid & 31;
    const int g    = lane >> 2, tq = lane & 3;
    const int wr   = (wid >> 2) * 64;
    const int wn   = wid & 3;
    const int wc   = wn * 32;
    const int row0 = blockIdx.x * 128;

    {
        const uint4* src = (const uint4*)(g_zh + row0 * D_OUT);
        uint4* dst = (uint4*)As;
        for (int idx = tid; idx < 2048; idx += 256) {
            int r = idx >> 4, c = idx & 15;
            dst[r * 17 + c] = src[idx];
        }
    }

    float rowAcc[4][2] = {};

    for (int ct = 0; ct < 8; ct++) {
        const int col0 = blockIdx.y * 1024 + ct * 128;
        __syncthreads();
        {
            const uint4* src = (const uint4*)(g_zh + col0 * D_OUT);
            uint4* dst = (uint4*)Bs;
            for (int idx = tid; idx < 2048; idx += 256) {
                int r = idx >> 4, c = idx & 15;
                dst[r * 17 + c] = src[idx];
            }
        }
        __syncthreads();

        float acc[4][4][4] = {};
        #pragma unroll
        for (int kk = 0; kk < 128; kk += 16) {
            uint32_t a[4][4], b[4][2];
            #pragma unroll
            for (int mi = 0; mi < 4; mi++) {
                const __nv_bfloat16* ap = As + (wr + mi * 16 + g) * SIM_TILE_STRIDE + kk + tq * 2;
                a[mi][0] = *(const uint32_t*)ap;
                a[mi][1] = *(const uint32_t*)(ap + 8 * SIM_TILE_STRIDE);
                a[mi][2] = *(const uint32_t*)(ap + 8);
                a[mi][3] = *(const uint32_t*)(ap + 8 * SIM_TILE_STRIDE + 8);
            }
            #pragma unroll
            for (int ni = 0; ni < 4; ni++) {
                const __nv_bfloat16* bp = Bs + (wc + ni * 8 + g) * SIM_TILE_STRIDE + kk + tq * 2;
                b[ni][0] = *(const uint32_t*)bp;
                b[ni][1] = *(const uint32_t*)(bp + 8);
            }
            #pragma unroll
            for (int mi = 0; mi < 4; mi++)
                #pragma unroll
                for (int ni = 0; ni < 4; ni++)
                    mma_bf16(acc[mi][ni], a[mi], b[ni]);
        }

        #pragma unroll
        for (int mi = 0; mi < 4; mi++) {
            const int r0 = row0 + wr + mi * 16 + g;
            const int r1 = r0 + 8;
            #pragma unroll
            for (int ni = 0; ni < 4; ni++) {
                const int j0 = col0 + wc + ni * 8 + tq * 2;
                float e00 = __expf(2.0f * acc[mi][ni][0]); if (j0     == r0) e00 = 0.f;
                float e01 = __expf(2.0f * acc[mi][ni][1]); if (j0 + 1 == r0) e01 = 0.f;
                float e10 = __expf(2.0f * acc[mi][ni][2]); if (j0     == r1) e10 = 0.f;
                float e11 = __expf(2.0f * acc[mi][ni][3]); if (j0 + 1 == r1) e11 = 0.f;
                rowAcc[mi][0] += e00 + e01;
                rowAcc[mi][1] += e10 + e11;
            }
        }
    }

    #pragma unroll
    for (int mi = 0; mi < 4; mi++)
        #pragma unroll
        for (int h = 0; h < 2; h++) {
            float s = rowAcc[mi][h];
            s += __shfl_xor_sync(0xffffffffu, s, 1);
            s += __shfl_xor_sync(0xffffffffu, s, 2);
            rowAcc[mi][h] = s;
        }

    __syncthreads();
    float* red = (float*)smem_bf;
    if (tq == 0) {
        #pragma unroll
        for (int mi = 0; mi < 4; mi++) {
            red[wn * 128 + wr + mi * 16 + g]     = rowAcc[mi][0];
            red[wn * 128 + wr + mi * 16 + g + 8] = rowAcc[mi][1];
        }
    }
    __syncthreads();
    if (tid < 128) {
        float s = red[tid] + red[128 + tid] + red[256 + tid] + red[384 + tid];
        g_partial[blockIdx.y * N2 + row0 + tid] = s;
    }
}

// ============================================================================
// loss = mean_i( log(sum_p partial[p][i]) - pos[i] )
// ============================================================================
__global__ void loss_kernel(float* __restrict__ out)
{
    __shared__ float sh[256];
    float s = 0.f;
    for (int i = threadIdx.x; i < N2; i += 256) {
        float se = 0.f;
        #pragma unroll
        for (int p = 0; p < 8; p++) se += g_partial[p * N2 + i];
        s += logf(se) - g_pos[i];
    }
    sh[threadIdx.x] = s;
    __syncthreads();
    for (int o = 128; o; o >>= 1) {
        if (threadIdx.x < o) sh[threadIdx.x] += sh[threadIdx.x + o];
        __syncthreads();
    }
    if (threadIdx.x == 0) out[0] = sh[0] * (1.0f / N2);
}

// ============================================================================
extern "C" void kernel_launch(void* const* d_in, const int* in_sizes, int n_in,
                              void* d_out, int out_size)
{
    const float* h1    = (const float*)d_in[0];
    const float* h2    = (const float*)d_in[1];
    const float* W1    = (const float*)d_in[2];
    const float* b1    = (const float*)d_in[3];
    const float* gamma = (const float*)d_in[4];
    const float* beta  = (const float*)d_in[5];
    const float* W2    = (const float*)d_in[6];
    const float* b2    = (const float*)d_in[7];
    float* out = (float*)d_out;

    cudaFuncSetAttribute(sim_kernel, cudaFuncAttributeMaxDynamicSharedMemorySize,
                         SIM_SMEM_BYTES);

    gemm1_kernel<<<dim3(N2 / 128, D_HID / 64), 256>>>(h1, h2, W1, b1);
    bn_stats_kernel<<<dim3(D_HID / 64, 2), dim3(64, 4)>>>(gamma, beta);
    gemm2_kernel<<<dim3(N2 / 128, D_OUT / 64), 256>>>(W2, b2);
    norm_kernel<<<N2 / 8, 256>>>(out);
    pos_kernel<<<BATCH / 8, 256>>>();
    sim_kernel<<<dim3(64, 8), 256, SIM_SMEM_BYTES>>>();
    loss_kernel<<<1, 256>>>(out);
}